// round 4
// baseline (speedup 1.0000x reference)
#include <cuda_runtime.h>
#include <cstdint>

#define IMG_W 200
#define CHAN 512
#define POOL 7
#define NROI 300

__device__ __forceinline__ uint32_t smem_u32(const void* p) {
    return (uint32_t)__cvta_generic_to_shared(p);
}

// grid = (49, 300). One block per pool position. Corner rows (2KB each) are
// fetched via cp.async.bulk into smem (bypassing the L1tex register-return
// path), then 128 threads lerp one float4 lane each.
__global__ void __launch_bounds__(128) roi_pool_tma_kernel(
    const float* __restrict__ img,   // [200,200,512]
    const int*   __restrict__ rois,  // [300,4] = (x,y,w,h)
    float*       __restrict__ out)   // [300,7,7,512]
{
    __shared__ alignas(128) float buf[4][CHAN];   // 8 KB
    __shared__ alignas(8) uint64_t mbar;

    const int gx  = blockIdx.x % POOL;
    const int gy  = blockIdx.x / POOL;
    const int roi = blockIdx.y;

    const int4 r = __ldg((const int4*)rois + roi);
    const int x0 = r.x, y0 = r.y, w = r.z, h = r.w;

    // Match reference numerics exactly.
    const float ys = (float)y0 + (float)gy * ((float)h / (float)POOL);
    const float xs = (float)x0 + (float)gx * ((float)w / (float)POOL);
    const int ty = (int)floorf(ys);
    const int tx = (int)floorf(xs);
    const float fy = ys - (float)ty;
    const float fx = xs - (float)tx;
    const int by = min(ty + 1, y0 + h - 1);
    const int bx = min(tx + 1, x0 + w - 1);

    const bool lx = (fx != 0.0f);   // x-neighbor has nonzero weight
    const bool ly = (fy != 0.0f);   // y-neighbor has nonzero weight

    const size_t o00 = ((size_t)ty * IMG_W + tx) * CHAN;
    const size_t o01 = ((size_t)ty * IMG_W + bx) * CHAN;
    const size_t o10 = ((size_t)by * IMG_W + tx) * CHAN;
    const size_t o11 = ((size_t)by * IMG_W + bx) * CHAN;

    const int tid = threadIdx.x;

    if (tid == 0) {
        const uint32_t mb = smem_u32(&mbar);
        asm volatile("mbarrier.init.shared.b64 [%0], 1;" :: "r"(mb) : "memory");
        asm volatile("fence.proxy.async.shared::cta;" ::: "memory");
    }
    __syncthreads();

    if (tid == 0) {
        const uint32_t mb = smem_u32(&mbar);
        const int nloads = 1 + (int)lx + (int)ly + (int)(lx && ly);
        const uint32_t txbytes = (uint32_t)nloads * (CHAN * 4);
        asm volatile("mbarrier.arrive.expect_tx.shared.b64 _, [%0], %1;"
                     :: "r"(mb), "r"(txbytes) : "memory");

        const uint32_t nb = CHAN * 4;  // 2048 bytes per corner row
        asm volatile("cp.async.bulk.shared::cluster.global.mbarrier::complete_tx::bytes "
                     "[%0], [%1], %2, [%3];"
                     :: "r"(smem_u32(buf[0])), "l"(img + o00), "r"(nb), "r"(mb) : "memory");
        if (lx)
            asm volatile("cp.async.bulk.shared::cluster.global.mbarrier::complete_tx::bytes "
                         "[%0], [%1], %2, [%3];"
                         :: "r"(smem_u32(buf[1])), "l"(img + o01), "r"(nb), "r"(mb) : "memory");
        if (ly)
            asm volatile("cp.async.bulk.shared::cluster.global.mbarrier::complete_tx::bytes "
                         "[%0], [%1], %2, [%3];"
                         :: "r"(smem_u32(buf[2])), "l"(img + o10), "r"(nb), "r"(mb) : "memory");
        if (lx && ly)
            asm volatile("cp.async.bulk.shared::cluster.global.mbarrier::complete_tx::bytes "
                         "[%0], [%1], %2, [%3];"
                         :: "r"(smem_u32(buf[3])), "l"(img + o11), "r"(nb), "r"(mb) : "memory");
    }

    // All threads wait for the bulk copies (parity phase 0).
    {
        const uint32_t mb = smem_u32(&mbar);
        asm volatile(
            "{\n\t"
            ".reg .pred P;\n\t"
            "WAIT_%=:\n\t"
            "mbarrier.try_wait.parity.acquire.cta.shared::cta.b64 P, [%0], 0, 0x989680;\n\t"
            "@P bra DONE_%=;\n\t"
            "bra WAIT_%=;\n\t"
            "DONE_%=:\n\t"
            "}"
            :: "r"(mb) : "memory");
    }

    const int c = tid;   // float4 lane 0..127
    const float4 v00 = ((const float4*)buf[0])[c];
    const float4 v01 = lx ? ((const float4*)buf[1])[c] : v00;
    const float4 v10 = ly ? ((const float4*)buf[2])[c] : v00;
    const float4 v11 = (lx && ly) ? ((const float4*)buf[3])[c] : (lx ? v01 : v10);

    const float omfx = 1.0f - fx;
    const float omfy = 1.0f - fy;

    float4 res;
    res.x = omfy * (omfx * v00.x + fx * v01.x) + fy * (omfx * v10.x + fx * v11.x);
    res.y = omfy * (omfx * v00.y + fx * v01.y) + fy * (omfx * v10.y + fx * v11.y);
    res.z = omfy * (omfx * v00.z + fx * v01.z) + fy * (omfx * v10.z + fx * v11.z);
    res.w = omfy * (omfx * v00.w + fx * v01.w) + fy * (omfx * v10.w + fx * v11.w);

    const size_t opos = ((size_t)roi * (POOL * POOL) + blockIdx.x) * (CHAN / 4) + c;
    ((float4*)out)[opos] = res;
}

extern "C" void kernel_launch(void* const* d_in, const int* in_sizes, int n_in,
                              void* d_out, int out_size) {
    const float* img  = (const float*)d_in[0];
    const int*   rois = (const int*)d_in[1];
    float*       out  = (float*)d_out;

    dim3 grid(POOL * POOL, NROI);   // (49, 300)
    roi_pool_tma_kernel<<<grid, 128>>>(img, rois, out);
}

// round 5
// speedup vs baseline: 1.1629x; 1.1629x over previous
#include <cuda_runtime.h>

#define IMG_W 200
#define CHAN 512
#define NF4  (CHAN / 4)      // 128 float4 per pixel row
#define POOL 7
#define NROI 300

// grid = (7, 300): blockIdx.x = gy, blockIdx.y = roi. 128 threads = one float4
// lane each. Each block produces 7 output positions (gx = 0..6), with a 2-slot
// software pipeline so gather latency overlaps lerp+store of the previous gx.
__global__ void __launch_bounds__(128) roi_pool_row_kernel(
    const float* __restrict__ img,   // [200,200,512]
    const int*   __restrict__ rois,  // [300,4] = (x,y,w,h)
    float*       __restrict__ out)   // [300,7,7,512]
{
    const int gy  = blockIdx.x;
    const int roi = blockIdx.y;
    const int c4  = threadIdx.x;     // float4 lane 0..127

    const int4 r = __ldg((const int4*)rois + roi);
    const int x0 = r.x, y0 = r.y, w = r.z, h = r.w;

    // y-setup once per block (reference numerics).
    const float ys = (float)y0 + (float)gy * ((float)h / (float)POOL);
    const int   ty = (int)floorf(ys);
    const float fy = ys - (float)ty;
    const int   by = min(ty + 1, y0 + h - 1);
    const bool  ly = (fy != 0.0f);

    const int rowt = ty * IMG_W;
    const int rowb = by * IMG_W;
    const float w7 = (float)w / (float)POOL;
    const int xmax = x0 + w - 1;

    const float4* __restrict__ base = (const float4*)img;
    float4* __restrict__ out4 = (float4*)out;
    const int obase = (roi * (POOL * POOL) + gy * POOL) * NF4 + c4;

    // Pipeline registers (2 slots).
    float4 s00[2], s01[2], s10[2], s11[2];
    float  fxs[2];

    // Issue gathers for position gx into pipeline slot `slot`.
    // Zero-weight corners alias an already-needed line (L1 hit, weight==0).
    #define ISSUE(gx_, slot_)                                                   \
    do {                                                                        \
        const float xs_ = (float)x0 + (float)(gx_) * w7;                        \
        const int   tx_ = (int)floorf(xs_);                                     \
        const float fx_ = xs_ - (float)tx_;                                     \
        const int   bx_ = min(tx_ + 1, xmax);                                   \
        const bool  lx_ = (fx_ != 0.0f);                                        \
        int o00_ = (rowt + tx_) * NF4;                                          \
        int o01_ = lx_ ? (rowt + bx_) * NF4 : o00_;                             \
        int o10_ = ly  ? (rowb + tx_) * NF4 : o00_;                             \
        int o11_ = lx_ ? (ly ? (rowb + bx_) * NF4 : o01_) : o10_;               \
        fxs[slot_] = fx_;                                                       \
        s00[slot_] = __ldg(base + o00_ + c4);                                   \
        s01[slot_] = __ldg(base + o01_ + c4);                                   \
        s10[slot_] = __ldg(base + o10_ + c4);                                   \
        s11[slot_] = __ldg(base + o11_ + c4);                                   \
    } while (0)

    ISSUE(0, 0);

    #pragma unroll
    for (int gx = 0; gx < POOL; gx++) {
        const int cur = gx & 1;
        if (gx < POOL - 1) ISSUE(gx + 1, cur ^ 1);

        const float fx  = fxs[cur];
        const float w00 = (1.0f - fy) * (1.0f - fx);
        const float w01 = (1.0f - fy) * fx;
        const float w10 = fy * (1.0f - fx);
        const float w11 = fy * fx;

        const float4 v00 = s00[cur], v01 = s01[cur];
        const float4 v10 = s10[cur], v11 = s11[cur];

        float4 res;
        res.x = w00 * v00.x + w01 * v01.x + w10 * v10.x + w11 * v11.x;
        res.y = w00 * v00.y + w01 * v01.y + w10 * v10.y + w11 * v11.y;
        res.z = w00 * v00.z + w01 * v01.z + w10 * v10.z + w11 * v11.z;
        res.w = w00 * v00.w + w01 * v01.w + w10 * v10.w + w11 * v11.w;

        out4[obase + gx * NF4] = res;
    }
    #undef ISSUE
}

extern "C" void kernel_launch(void* const* d_in, const int* in_sizes, int n_in,
                              void* d_out, int out_size) {
    const float* img  = (const float*)d_in[0];
    const int*   rois = (const int*)d_in[1];
    float*       out  = (float*)d_out;

    dim3 grid(POOL, NROI);   // (7, 300) = 2100 blocks
    roi_pool_row_kernel<<<grid, 128>>>(img, rois, out);
}